// round 1
// baseline (speedup 1.0000x reference)
#include <cuda_runtime.h>
#include <math.h>

// Problem constants
#define Bb 2
#define Tt 2048
#define Ee 2048
#define BT (Bb*Tt)          // 4096
#define Hh 16
#define HKV 4
#define MM 4
#define HD 32
#define EKV 512
#define HALF 16             // HD/2
#define SCALEF 0.17677669529663687f  // 1/sqrt(32)

// -------- scratch buffers (no cudaMalloc allowed) --------
__device__ __align__(128) float g_q[(size_t)BT * Ee];      // q proj + rope
__device__ __align__(128) float g_k[(size_t)BT * EKV];     // k proj + rope
__device__ __align__(128) float g_v[(size_t)BT * EKV];     // v proj
__device__ __align__(128) float g_L[(size_t)Bb * Hh * MM * Tt]; // softmax row sums
__device__ __align__(128) float g_n[(size_t)BT * Ee];      // combined+rmsnorm

// ============================================================
// SGEMM: C[m,n] = sum_k A[m,k] * W[n,k]   (A: 4096 x K, W: N x K)
// 128x128 tile, BK=16, 256 threads, 8x8 per thread.
// Optional fused interleaved RoPE epilogue (pairs within 32-dim chunks).
// ============================================================
template<int ROPE>
__global__ __launch_bounds__(256)
void sgemm_tn(const float* __restrict__ A, const float* __restrict__ W,
              float* __restrict__ C, int N, int K,
              const float* __restrict__ cosp, const float* __restrict__ sinp)
{
    __shared__ float As[16][132];
    __shared__ float Bs[16][132];

    const int tid = threadIdx.x;
    const int tx = tid & 15;
    const int ty = tid >> 4;
    const int m0 = blockIdx.y * 128;
    const int n0 = blockIdx.x * 128;

    float acc[8][8];
#pragma unroll
    for (int i = 0; i < 8; ++i)
#pragma unroll
        for (int j = 0; j < 8; ++j) acc[i][j] = 0.f;

    for (int k0 = 0; k0 < K; k0 += 16) {
#pragma unroll
        for (int it = 0; it < 2; ++it) {
            int idx = tid + it * 256;          // 0..511
            int row = idx >> 2;                // 0..127
            int kq  = (idx & 3) << 2;          // 0,4,8,12
            float4 a = *(const float4*)(A + (size_t)(m0 + row) * K + k0 + kq);
            As[kq + 0][row] = a.x; As[kq + 1][row] = a.y;
            As[kq + 2][row] = a.z; As[kq + 3][row] = a.w;
            float4 w = *(const float4*)(W + (size_t)(n0 + row) * K + k0 + kq);
            Bs[kq + 0][row] = w.x; Bs[kq + 1][row] = w.y;
            Bs[kq + 2][row] = w.z; Bs[kq + 3][row] = w.w;
        }
        __syncthreads();
#pragma unroll
        for (int kk = 0; kk < 16; ++kk) {
            float ar[8], br[8];
            *(float4*)(ar)     = *(const float4*)&As[kk][ty * 8];
            *(float4*)(ar + 4) = *(const float4*)&As[kk][ty * 8 + 4];
            *(float4*)(br)     = *(const float4*)&Bs[kk][tx * 8];
            *(float4*)(br + 4) = *(const float4*)&Bs[kk][tx * 8 + 4];
#pragma unroll
            for (int i = 0; i < 8; ++i)
#pragma unroll
                for (int j = 0; j < 8; ++j)
                    acc[i][j] += ar[i] * br[j];
        }
        __syncthreads();
    }

#pragma unroll
    for (int ii = 0; ii < 8; ++ii) {
        int row = m0 + ty * 8 + ii;
        if (ROPE) {
            int t = row & (Tt - 1);
#pragma unroll
            for (int jj = 0; jj < 8; jj += 2) {
                int n = n0 + tx * 8 + jj;
                int p = (n & 31) >> 1;
                float c = cosp[t * HALF + p];
                float s = sinp[t * HALF + p];
                float ev = acc[ii][jj], ov = acc[ii][jj + 1];
                acc[ii][jj]     = ev * c - ov * s;
                acc[ii][jj + 1] = ev * s + ov * c;
            }
        }
        float4 o0 = make_float4(acc[ii][0], acc[ii][1], acc[ii][2], acc[ii][3]);
        float4 o1 = make_float4(acc[ii][4], acc[ii][5], acc[ii][6], acc[ii][7]);
        float* cp = C + (size_t)row * N + n0 + tx * 8;
        *(float4*)(cp)     = o0;
        *(float4*)(cp + 4) = o1;
    }
}

// ------------------------------------------------------------
// load a 64-row x 128-col fp32 tile from global (rowstride) into
// shared memory with per-row stride `dstride` (floats). 256 threads.
// ------------------------------------------------------------
__device__ __forceinline__
void load_tile64x128(const float* __restrict__ base, int rowstride,
                     float* __restrict__ dst, int dstride, int tid)
{
#pragma unroll
    for (int it = 0; it < 8; ++it) {
        int idx = tid + it * 256;      // 0..2047
        int row = idx >> 5;            // 0..63
        int cq  = (idx & 31) << 2;     // 0..124
        float4 a = *(const float4*)(base + (size_t)row * rowstride + cq);
        float* d = dst + row * dstride + cq;
        d[0] = a.x; d[1] = a.y; d[2] = a.z; d[3] = a.w;
    }
}

// ============================================================
// Attention pass 1: softmax denominators per (b,h,member,t)
// scores are bounded -> no running max needed.
// grid: (T/64, H, B), 256 threads.
// ============================================================
#define P1_QS 0
#define P1_KS (64*129)
#define P1_RED (2*64*129)
#define P1_SMEM_BYTES ((2*64*129 + 64*16) * 4)

__global__ __launch_bounds__(256)
void attn_pass1()
{
    extern __shared__ float sm[];
    float* qs  = sm + P1_QS;
    float* ks  = sm + P1_KS;
    float* red = sm + P1_RED;

    const int tid = threadIdx.x;
    const int tx = tid & 15;
    const int ty = tid >> 4;
    const int qt = blockIdx.x;
    const int h  = blockIdx.y;
    const int b  = blockIdx.z;
    const int g  = h >> 2;
    const int t0 = qt * 64;

    load_tile64x128(g_q + ((size_t)(b * Tt + t0)) * Ee + h * 128, Ee, qs, 129, tid);

    float rs[MM][4];
#pragma unroll
    for (int i = 0; i < MM; ++i)
#pragma unroll
        for (int ii = 0; ii < 4; ++ii) rs[i][ii] = 0.f;

    for (int st = 0; st <= qt; ++st) {
        int s0 = st * 64;
        load_tile64x128(g_k + ((size_t)(b * Tt + s0)) * EKV + g * 128, EKV, ks, 129, tid);
        __syncthreads();
        const bool diag = (st == qt);
#pragma unroll
        for (int i = 0; i < MM; ++i) {
            float acc[4][4];
#pragma unroll
            for (int ii = 0; ii < 4; ++ii)
#pragma unroll
                for (int jj = 0; jj < 4; ++jj) acc[ii][jj] = 0.f;
            const float* qb = qs + (ty * 4) * 129 + i * HD;
            const float* kb = ks + (tx * 4) * 129 + i * HD;
#pragma unroll 8
            for (int d = 0; d < HD; ++d) {
                float q0 = qb[d], q1 = qb[129 + d], q2 = qb[258 + d], q3 = qb[387 + d];
                float k0 = kb[d], k1 = kb[129 + d], k2 = kb[258 + d], k3 = kb[387 + d];
                acc[0][0] += q0 * k0; acc[0][1] += q0 * k1; acc[0][2] += q0 * k2; acc[0][3] += q0 * k3;
                acc[1][0] += q1 * k0; acc[1][1] += q1 * k1; acc[1][2] += q1 * k2; acc[1][3] += q1 * k3;
                acc[2][0] += q2 * k0; acc[2][1] += q2 * k1; acc[2][2] += q2 * k2; acc[2][3] += q2 * k3;
                acc[3][0] += q3 * k0; acc[3][1] += q3 * k1; acc[3][2] += q3 * k2; acc[3][3] += q3 * k3;
            }
#pragma unroll
            for (int ii = 0; ii < 4; ++ii)
#pragma unroll
                for (int jj = 0; jj < 4; ++jj) {
                    if (!diag || (tx * 4 + jj) <= (ty * 4 + ii))
                        rs[i][ii] += __expf(acc[ii][jj] * SCALEF);
                }
        }
        __syncthreads();
    }

    // reduce across the 16 column-threads per row
    for (int i = 0; i < MM; ++i) {
#pragma unroll
        for (int ii = 0; ii < 4; ++ii)
            red[(ty * 4 + ii) * 16 + tx] = rs[i][ii];
        __syncthreads();
        if (tid < 64) {
            float s = 0.f;
#pragma unroll
            for (int u = 0; u < 16; ++u) s += red[tid * 16 + u];
            g_L[(((size_t)b * Hh + h) * MM + i) * Tt + t0 + tid] = s;
        }
        __syncthreads();
    }
}

// ============================================================
// Attention pass 2: combined = sum_i (w_i/l_i) exp(S_i) @ V, fused RMSNorm
// grid: (T/64, H, B), 256 threads.
// ============================================================
#define P2_QS   0
#define P2_KS   (64*129)
#define P2_VS   (2*64*129)
#define P2_PS   (2*64*129 + 64*132)
#define P2_LI   (P2_PS + 64*65)
#define P2_RED  (P2_LI + 4*64)
#define P2_SMEM_BYTES ((P2_RED + 64*16) * 4)

__global__ __launch_bounds__(256)
void attn_pass2(const float* __restrict__ raw_w,
                const float* __restrict__ wscale,
                const float* __restrict__ gamma)
{
    extern __shared__ float sm[];
    float* qs   = sm + P2_QS;
    float* ks   = sm + P2_KS;
    float* vs   = sm + P2_VS;
    float* ps   = sm + P2_PS;
    float* linv = sm + P2_LI;
    float* red  = sm + P2_RED;

    const int tid = threadIdx.x;
    const int tx = tid & 15;
    const int ty = tid >> 4;
    const int qt = blockIdx.x;
    const int h  = blockIdx.y;
    const int b  = blockIdx.z;
    const int g  = h >> 2;
    const int t0 = qt * 64;

    if (tid < 64) {
        float ws = wscale[0];
#pragma unroll
        for (int i = 0; i < MM; ++i) {
            float wi = tanhf(raw_w[i]) * ws;
            float l = g_L[(((size_t)b * Hh + h) * MM + i) * Tt + t0 + tid];
            linv[i * 64 + tid] = wi / l;
        }
    }
    load_tile64x128(g_q + ((size_t)(b * Tt + t0)) * Ee + h * 128, Ee, qs, 129, tid);

    float gm[8];
#pragma unroll
    for (int jj = 0; jj < 8; ++jj) gm[jj] = gamma[tx * 8 + jj];

    float o[4][8];
#pragma unroll
    for (int ii = 0; ii < 4; ++ii)
#pragma unroll
        for (int jj = 0; jj < 8; ++jj) o[ii][jj] = 0.f;

    for (int st = 0; st <= qt; ++st) {
        int s0 = st * 64;
        load_tile64x128(g_k + ((size_t)(b * Tt + s0)) * EKV + g * 128, EKV, ks, 129, tid);
        load_tile64x128(g_v + ((size_t)(b * Tt + s0)) * EKV + g * 128, EKV, vs, 132, tid);
        __syncthreads();

        const bool diag = (st == qt);
        float pacc[4][4];
#pragma unroll
        for (int ii = 0; ii < 4; ++ii)
#pragma unroll
            for (int jj = 0; jj < 4; ++jj) pacc[ii][jj] = 0.f;

#pragma unroll
        for (int i = 0; i < MM; ++i) {
            float acc[4][4];
#pragma unroll
            for (int ii = 0; ii < 4; ++ii)
#pragma unroll
                for (int jj = 0; jj < 4; ++jj) acc[ii][jj] = 0.f;
            const float* qb = qs + (ty * 4) * 129 + i * HD;
            const float* kb = ks + (tx * 4) * 129 + i * HD;
#pragma unroll 8
            for (int d = 0; d < HD; ++d) {
                float q0 = qb[d], q1 = qb[129 + d], q2 = qb[258 + d], q3 = qb[387 + d];
                float k0 = kb[d], k1 = kb[129 + d], k2 = kb[258 + d], k3 = kb[387 + d];
                acc[0][0] += q0 * k0; acc[0][1] += q0 * k1; acc[0][2] += q0 * k2; acc[0][3] += q0 * k3;
                acc[1][0] += q1 * k0; acc[1][1] += q1 * k1; acc[1][2] += q1 * k2; acc[1][3] += q1 * k3;
                acc[2][0] += q2 * k0; acc[2][1] += q2 * k1; acc[2][2] += q2 * k2; acc[2][3] += q2 * k3;
                acc[3][0] += q3 * k0; acc[3][1] += q3 * k1; acc[3][2] += q3 * k2; acc[3][3] += q3 * k3;
            }
            float li0 = linv[i * 64 + ty * 4 + 0];
            float li1 = linv[i * 64 + ty * 4 + 1];
            float li2 = linv[i * 64 + ty * 4 + 2];
            float li3 = linv[i * 64 + ty * 4 + 3];
#pragma unroll
            for (int jj = 0; jj < 4; ++jj) {
                pacc[0][jj] += li0 * __expf(acc[0][jj] * SCALEF);
                pacc[1][jj] += li1 * __expf(acc[1][jj] * SCALEF);
                pacc[2][jj] += li2 * __expf(acc[2][jj] * SCALEF);
                pacc[3][jj] += li3 * __expf(acc[3][jj] * SCALEF);
            }
        }
        // causal mask (diagonal tile only) + stage P into smem
#pragma unroll
        for (int ii = 0; ii < 4; ++ii)
#pragma unroll
            for (int jj = 0; jj < 4; ++jj) {
                float pv = pacc[ii][jj];
                if (diag && (tx * 4 + jj) > (ty * 4 + ii)) pv = 0.f;
                ps[(ty * 4 + ii) * 65 + tx * 4 + jj] = pv;
            }
        __syncthreads();

        // O += P @ V   (64x64 @ 64x128)
#pragma unroll 4
        for (int s = 0; s < 64; ++s) {
            float p0 = ps[(ty * 4 + 0) * 65 + s];
            float p1 = ps[(ty * 4 + 1) * 65 + s];
            float p2 = ps[(ty * 4 + 2) * 65 + s];
            float p3 = ps[(ty * 4 + 3) * 65 + s];
            float vr[8];
            *(float4*)(vr)     = *(const float4*)&vs[s * 132 + tx * 8];
            *(float4*)(vr + 4) = *(const float4*)&vs[s * 132 + tx * 8 + 4];
#pragma unroll
            for (int jj = 0; jj < 8; ++jj) {
                o[0][jj] += p0 * vr[jj];
                o[1][jj] += p1 * vr[jj];
                o[2][jj] += p2 * vr[jj];
                o[3][jj] += p3 * vr[jj];
            }
        }
        __syncthreads();
    }

    // fused RMSNorm over the 128 dims owned by this CTA
#pragma unroll
    for (int ii = 0; ii < 4; ++ii) {
        float sq = 0.f;
#pragma unroll
        for (int jj = 0; jj < 8; ++jj) sq += o[ii][jj] * o[ii][jj];
        red[(ty * 4 + ii) * 16 + tx] = sq;
    }
    __syncthreads();
    if (tid < 64) {
        float ssum = 0.f;
#pragma unroll
        for (int u = 0; u < 16; ++u) ssum += red[tid * 16 + u];
        ps[tid] = rsqrtf(ssum * (1.f / 128.f) + 1e-5f);
    }
    __syncthreads();
#pragma unroll
    for (int ii = 0; ii < 4; ++ii) {
        int row = t0 + ty * 4 + ii;
        float rn = ps[ty * 4 + ii];
        float4 o0 = make_float4(o[ii][0] * rn * gm[0], o[ii][1] * rn * gm[1],
                                o[ii][2] * rn * gm[2], o[ii][3] * rn * gm[3]);
        float4 o1 = make_float4(o[ii][4] * rn * gm[4], o[ii][5] * rn * gm[5],
                                o[ii][6] * rn * gm[6], o[ii][7] * rn * gm[7]);
        float* np = g_n + ((size_t)(b * Tt + row)) * Ee + h * 128 + tx * 8;
        *(float4*)(np)     = o0;
        *(float4*)(np + 4) = o1;
    }
}

// ============================================================
extern "C" void kernel_launch(void* const* d_in, const int* in_sizes, int n_in,
                              void* d_out, int out_size)
{
    const float* x      = (const float*)d_in[0];
    const float* cosp   = (const float*)d_in[1];
    const float* sinp   = (const float*)d_in[2];
    const float* q_w    = (const float*)d_in[3];
    const float* k_w    = (const float*)d_in[4];
    const float* v_w    = (const float*)d_in[5];
    const float* out_w  = (const float*)d_in[6];
    const float* raw_w  = (const float*)d_in[7];
    const float* wscale = (const float*)d_in[8];
    const float* gamma  = (const float*)d_in[9];

    float *qb, *kb, *vb, *nb;
    cudaGetSymbolAddress((void**)&qb, g_q);
    cudaGetSymbolAddress((void**)&kb, g_k);
    cudaGetSymbolAddress((void**)&vb, g_v);
    cudaGetSymbolAddress((void**)&nb, g_n);

    cudaFuncSetAttribute(attn_pass1, cudaFuncAttributeMaxDynamicSharedMemorySize, P1_SMEM_BYTES);
    cudaFuncSetAttribute(attn_pass2, cudaFuncAttributeMaxDynamicSharedMemorySize, P2_SMEM_BYTES);

    dim3 blk(256);

    // projections (rope fused into q,k)
    sgemm_tn<1><<<dim3(Ee / 128, BT / 128), blk>>>(x, q_w, qb, Ee, Ee, cosp, sinp);
    sgemm_tn<1><<<dim3(EKV / 128, BT / 128), blk>>>(x, k_w, kb, EKV, Ee, cosp, sinp);
    sgemm_tn<0><<<dim3(EKV / 128, BT / 128), blk>>>(x, v_w, vb, EKV, Ee, nullptr, nullptr);

    // attention (2-pass, ensemble-combined P, fused RMSNorm)
    dim3 agrid(Tt / 64, Hh, Bb);
    attn_pass1<<<agrid, blk, P1_SMEM_BYTES>>>();
    attn_pass2<<<agrid, blk, P2_SMEM_BYTES>>>(raw_w, wscale, gamma);

    // output projection
    sgemm_tn<0><<<dim3(Ee / 128, BT / 128), blk>>>(nb, out_w, (float*)d_out, Ee, Ee, nullptr, nullptr);
}

// round 2
// speedup vs baseline: 1.5172x; 1.5172x over previous
#include <cuda_runtime.h>
#include <math.h>

// Problem constants
#define Bb 2
#define Tt 2048
#define Ee 2048
#define BT (Bb*Tt)          // 4096
#define Hh 16
#define HKV 4
#define MM 4
#define HD 32
#define EKV 512
#define HALF 16             // HD/2
#define SCALEF 0.17677669529663687f  // 1/sqrt(32)

// -------- scratch buffers (no cudaMalloc allowed) --------
__device__ __align__(128) float g_q[(size_t)BT * Ee];      // q proj + rope
__device__ __align__(128) float g_k[(size_t)BT * EKV];     // k proj + rope
__device__ __align__(128) float g_v[(size_t)BT * EKV];     // v proj
__device__ __align__(128) float g_L[(size_t)Bb * Hh * MM * Tt]; // softmax row sums
__device__ __align__(128) float g_n[(size_t)BT * Ee];      // combined+rmsnorm

// ============================================================
// tf32 tensor-core GEMM: C[m,n] = sum_k A[m,k] * W[n,k]
// (A: M x K row-major, W: N x K row-major -> classic TN)
// CTA tile 128x128, BK=16, 128 threads = 4 warps (2x2),
// warp tile 64x64 = 4x8 mma.m16n8k8 fragments.
// Smem stored [row][k] with row stride 20 floats -> fragment
// loads are provably bank-conflict-free.
// cp.async 2-stage pipeline. Optional fused interleaved RoPE.
// ============================================================
#define BM 128
#define BN 128
#define BKt 16
#define STRIDE 20

__device__ __forceinline__ void cp_issue_tile(
    const float* __restrict__ A, const float* __restrict__ W,
    int K, int m0, int n0, int k0,
    float* __restrict__ asb, float* __restrict__ bsb, int tid)
{
#pragma unroll
    for (int i = 0; i < 4; ++i) {
        int idx = tid + i * 128;       // 0..511
        int row = idx >> 2;            // 0..127
        int kq  = (idx & 3) << 2;      // 0,4,8,12
        const float* gA = A + (size_t)(m0 + row) * K + k0 + kq;
        unsigned sA = (unsigned)__cvta_generic_to_shared(asb + row * STRIDE + kq);
        asm volatile("cp.async.ca.shared.global [%0], [%1], 16;\n" :: "r"(sA), "l"(gA));
        const float* gW = W + (size_t)(n0 + row) * K + k0 + kq;
        unsigned sB = (unsigned)__cvta_generic_to_shared(bsb + row * STRIDE + kq);
        asm volatile("cp.async.ca.shared.global [%0], [%1], 16;\n" :: "r"(sB), "l"(gW));
    }
    asm volatile("cp.async.commit_group;\n");
}

__device__ __forceinline__ unsigned to_tf32(float f)
{
    unsigned u;
    asm("cvt.rna.tf32.f32 %0, %1;\n" : "=r"(u) : "f"(f));
    return u;
}

template<int ROPE>
__global__ __launch_bounds__(128)
void gemm_tf32(const float* __restrict__ A, const float* __restrict__ W,
               float* __restrict__ C, int N, int K,
               const float* __restrict__ cosp, const float* __restrict__ sinp)
{
    __shared__ float As[2][BM * STRIDE];
    __shared__ float Bs[2][BN * STRIDE];

    const int tid  = threadIdx.x;
    const int lane = tid & 31;
    const int warp = tid >> 5;
    const int g    = lane >> 2;   // groupID
    const int tig  = lane & 3;    // threadID in group
    const int wm   = warp >> 1;   // 0..1
    const int wn   = warp & 1;    // 0..1
    const int m0 = blockIdx.y * BM;
    const int n0 = blockIdx.x * BN;

    float c[4][8][4];
#pragma unroll
    for (int mt = 0; mt < 4; ++mt)
#pragma unroll
        for (int nt = 0; nt < 8; ++nt)
#pragma unroll
            for (int r = 0; r < 4; ++r) c[mt][nt][r] = 0.f;

    cp_issue_tile(A, W, K, m0, n0, 0, As[0], Bs[0], tid);

    const int NT = K / BKt;
    for (int kt = 0; kt < NT; ++kt) {
        if (kt + 1 < NT)
            cp_issue_tile(A, W, K, m0, n0, (kt + 1) * BKt,
                          As[(kt + 1) & 1], Bs[(kt + 1) & 1], tid);
        else
            asm volatile("cp.async.commit_group;\n");
        asm volatile("cp.async.wait_group 1;\n");
        __syncthreads();

        const float* as = &As[kt & 1][(wm * 64 + g) * STRIDE + tig];
        const float* bs = &Bs[kt & 1][(wn * 64 + g) * STRIDE + tig];

#pragma unroll
        for (int ks = 0; ks < BKt; ks += 8) {
            unsigned a[4][4], b[8][2];
#pragma unroll
            for (int mt = 0; mt < 4; ++mt) {
                a[mt][0] = to_tf32(as[(mt * 16    ) * STRIDE + ks    ]);
                a[mt][1] = to_tf32(as[(mt * 16 + 8) * STRIDE + ks    ]);
                a[mt][2] = to_tf32(as[(mt * 16    ) * STRIDE + ks + 4]);
                a[mt][3] = to_tf32(as[(mt * 16 + 8) * STRIDE + ks + 4]);
            }
#pragma unroll
            for (int nt = 0; nt < 8; ++nt) {
                b[nt][0] = to_tf32(bs[(nt * 8) * STRIDE + ks    ]);
                b[nt][1] = to_tf32(bs[(nt * 8) * STRIDE + ks + 4]);
            }
#pragma unroll
            for (int mt = 0; mt < 4; ++mt)
#pragma unroll
                for (int nt = 0; nt < 8; ++nt) {
                    asm volatile(
                        "mma.sync.aligned.m16n8k8.row.col.f32.tf32.tf32.f32 "
                        "{%0,%1,%2,%3}, {%4,%5,%6,%7}, {%8,%9}, {%0,%1,%2,%3};\n"
                        : "+f"(c[mt][nt][0]), "+f"(c[mt][nt][1]),
                          "+f"(c[mt][nt][2]), "+f"(c[mt][nt][3])
                        : "r"(a[mt][0]), "r"(a[mt][1]), "r"(a[mt][2]), "r"(a[mt][3]),
                          "r"(b[nt][0]), "r"(b[nt][1]));
                }
        }
        __syncthreads();
    }

    // epilogue: rows mA=..+g and mB=..+g+8; cols come in adjacent (even,odd)
    // pairs (2*tig, 2*tig+1) -> RoPE applies directly to (c0,c1)/(c2,c3).
#pragma unroll
    for (int mt = 0; mt < 4; ++mt) {
        int mA = m0 + wm * 64 + mt * 16 + g;
        int mB = mA + 8;
#pragma unroll
        for (int nt = 0; nt < 8; ++nt) {
            int n = n0 + wn * 64 + nt * 8 + tig * 2;
            float v0 = c[mt][nt][0], v1 = c[mt][nt][1];
            float v2 = c[mt][nt][2], v3 = c[mt][nt][3];
            if (ROPE) {
                int p = (n & 31) >> 1;
                int tA = mA & (Tt - 1), tB = mB & (Tt - 1);
                float cA = cosp[tA * HALF + p], snA = sinp[tA * HALF + p];
                float cB = cosp[tB * HALF + p], snB = sinp[tB * HALF + p];
                float e = v0, o = v1;
                v0 = e * cA - o * snA; v1 = e * snA + o * cA;
                e = v2; o = v3;
                v2 = e * cB - o * snB; v3 = e * snB + o * cB;
            }
            *(float2*)(C + (size_t)mA * N + n) = make_float2(v0, v1);
            *(float2*)(C + (size_t)mB * N + n) = make_float2(v2, v3);
        }
    }
}

// ------------------------------------------------------------
// load a 64-row x 128-col fp32 tile from global (rowstride) into
// shared memory with per-row stride `dstride` (floats). 256 threads.
// ------------------------------------------------------------
__device__ __forceinline__
void load_tile64x128(const float* __restrict__ base, int rowstride,
                     float* __restrict__ dst, int dstride, int tid)
{
#pragma unroll
    for (int it = 0; it < 8; ++it) {
        int idx = tid + it * 256;      // 0..2047
        int row = idx >> 5;            // 0..63
        int cq  = (idx & 31) << 2;     // 0..124
        float4 a = *(const float4*)(base + (size_t)row * rowstride + cq);
        float* d = dst + row * dstride + cq;
        d[0] = a.x; d[1] = a.y; d[2] = a.z; d[3] = a.w;
    }
}

// ============================================================
// Attention pass 1: softmax denominators per (b,h,member,t)
// scores are bounded -> no running max needed.
// grid: (T/64, H, B), 256 threads.
// ============================================================
#define P1_QS 0
#define P1_KS (64*129)
#define P1_RED (2*64*129)
#define P1_SMEM_BYTES ((2*64*129 + 64*16) * 4)

__global__ __launch_bounds__(256)
void attn_pass1()
{
    extern __shared__ float sm[];
    float* qs  = sm + P1_QS;
    float* ks  = sm + P1_KS;
    float* red = sm + P1_RED;

    const int tid = threadIdx.x;
    const int tx = tid & 15;
    const int ty = tid >> 4;
    const int qt = blockIdx.x;
    const int h  = blockIdx.y;
    const int b  = blockIdx.z;
    const int g  = h >> 2;
    const int t0 = qt * 64;

    load_tile64x128(g_q + ((size_t)(b * Tt + t0)) * Ee + h * 128, Ee, qs, 129, tid);

    float rs[MM][4];
#pragma unroll
    for (int i = 0; i < MM; ++i)
#pragma unroll
        for (int ii = 0; ii < 4; ++ii) rs[i][ii] = 0.f;

    for (int st = 0; st <= qt; ++st) {
        int s0 = st * 64;
        load_tile64x128(g_k + ((size_t)(b * Tt + s0)) * EKV + g * 128, EKV, ks, 129, tid);
        __syncthreads();
        const bool diag = (st == qt);
#pragma unroll
        for (int i = 0; i < MM; ++i) {
            float acc[4][4];
#pragma unroll
            for (int ii = 0; ii < 4; ++ii)
#pragma unroll
                for (int jj = 0; jj < 4; ++jj) acc[ii][jj] = 0.f;
            const float* qb = qs + (ty * 4) * 129 + i * HD;
            const float* kb = ks + (tx * 4) * 129 + i * HD;
#pragma unroll 8
            for (int d = 0; d < HD; ++d) {
                float q0 = qb[d], q1 = qb[129 + d], q2 = qb[258 + d], q3 = qb[387 + d];
                float k0 = kb[d], k1 = kb[129 + d], k2 = kb[258 + d], k3 = kb[387 + d];
                acc[0][0] += q0 * k0; acc[0][1] += q0 * k1; acc[0][2] += q0 * k2; acc[0][3] += q0 * k3;
                acc[1][0] += q1 * k0; acc[1][1] += q1 * k1; acc[1][2] += q1 * k2; acc[1][3] += q1 * k3;
                acc[2][0] += q2 * k0; acc[2][1] += q2 * k1; acc[2][2] += q2 * k2; acc[2][3] += q2 * k3;
                acc[3][0] += q3 * k0; acc[3][1] += q3 * k1; acc[3][2] += q3 * k2; acc[3][3] += q3 * k3;
            }
#pragma unroll
            for (int ii = 0; ii < 4; ++ii)
#pragma unroll
                for (int jj = 0; jj < 4; ++jj) {
                    if (!diag || (tx * 4 + jj) <= (ty * 4 + ii))
                        rs[i][ii] += __expf(acc[ii][jj] * SCALEF);
                }
        }
        __syncthreads();
    }

    // reduce across the 16 column-threads per row
    for (int i = 0; i < MM; ++i) {
#pragma unroll
        for (int ii = 0; ii < 4; ++ii)
            red[(ty * 4 + ii) * 16 + tx] = rs[i][ii];
        __syncthreads();
        if (tid < 64) {
            float s = 0.f;
#pragma unroll
            for (int u = 0; u < 16; ++u) s += red[tid * 16 + u];
            g_L[(((size_t)b * Hh + h) * MM + i) * Tt + t0 + tid] = s;
        }
        __syncthreads();
    }
}

// ============================================================
// Attention pass 2: combined = sum_i (w_i/l_i) exp(S_i) @ V, fused RMSNorm
// grid: (T/64, H, B), 256 threads.
// ============================================================
#define P2_QS   0
#define P2_KS   (64*129)
#define P2_VS   (2*64*129)
#define P2_PS   (2*64*129 + 64*132)
#define P2_LI   (P2_PS + 64*65)
#define P2_RED  (P2_LI + 4*64)
#define P2_SMEM_BYTES ((P2_RED + 64*16) * 4)

__global__ __launch_bounds__(256)
void attn_pass2(const float* __restrict__ raw_w,
                const float* __restrict__ wscale,
                const float* __restrict__ gamma)
{
    extern __shared__ float sm[];
    float* qs   = sm + P2_QS;
    float* ks   = sm + P2_KS;
    float* vs   = sm + P2_VS;
    float* ps   = sm + P2_PS;
    float* linv = sm + P2_LI;
    float* red  = sm + P2_RED;

    const int tid = threadIdx.x;
    const int tx = tid & 15;
    const int ty = tid >> 4;
    const int qt = blockIdx.x;
    const int h  = blockIdx.y;
    const int b  = blockIdx.z;
    const int g  = h >> 2;
    const int t0 = qt * 64;

    if (tid < 64) {
        float ws = wscale[0];
#pragma unroll
        for (int i = 0; i < MM; ++i) {
            float wi = tanhf(raw_w[i]) * ws;
            float l = g_L[(((size_t)b * Hh + h) * MM + i) * Tt + t0 + tid];
            linv[i * 64 + tid] = wi / l;
        }
    }
    load_tile64x128(g_q + ((size_t)(b * Tt + t0)) * Ee + h * 128, Ee, qs, 129, tid);

    float gm[8];
#pragma unroll
    for (int jj = 0; jj < 8; ++jj) gm[jj] = gamma[tx * 8 + jj];

    float o[4][8];
#pragma unroll
    for (int ii = 0; ii < 4; ++ii)
#pragma unroll
        for (int jj = 0; jj < 8; ++jj) o[ii][jj] = 0.f;

    for (int st = 0; st <= qt; ++st) {
        int s0 = st * 64;
        load_tile64x128(g_k + ((size_t)(b * Tt + s0)) * EKV + g * 128, EKV, ks, 129, tid);
        load_tile64x128(g_v + ((size_t)(b * Tt + s0)) * EKV + g * 128, EKV, vs, 132, tid);
        __syncthreads();

        const bool diag = (st == qt);
        float pacc[4][4];
#pragma unroll
        for (int ii = 0; ii < 4; ++ii)
#pragma unroll
            for (int jj = 0; jj < 4; ++jj) pacc[ii][jj] = 0.f;

#pragma unroll
        for (int i = 0; i < MM; ++i) {
            float acc[4][4];
#pragma unroll
            for (int ii = 0; ii < 4; ++ii)
#pragma unroll
                for (int jj = 0; jj < 4; ++jj) acc[ii][jj] = 0.f;
            const float* qb = qs + (ty * 4) * 129 + i * HD;
            const float* kb = ks + (tx * 4) * 129 + i * HD;
#pragma unroll 8
            for (int d = 0; d < HD; ++d) {
                float q0 = qb[d], q1 = qb[129 + d], q2 = qb[258 + d], q3 = qb[387 + d];
                float k0 = kb[d], k1 = kb[129 + d], k2 = kb[258 + d], k3 = kb[387 + d];
                acc[0][0] += q0 * k0; acc[0][1] += q0 * k1; acc[0][2] += q0 * k2; acc[0][3] += q0 * k3;
                acc[1][0] += q1 * k0; acc[1][1] += q1 * k1; acc[1][2] += q1 * k2; acc[1][3] += q1 * k3;
                acc[2][0] += q2 * k0; acc[2][1] += q2 * k1; acc[2][2] += q2 * k2; acc[2][3] += q2 * k3;
                acc[3][0] += q3 * k0; acc[3][1] += q3 * k1; acc[3][2] += q3 * k2; acc[3][3] += q3 * k3;
            }
            float li0 = linv[i * 64 + ty * 4 + 0];
            float li1 = linv[i * 64 + ty * 4 + 1];
            float li2 = linv[i * 64 + ty * 4 + 2];
            float li3 = linv[i * 64 + ty * 4 + 3];
#pragma unroll
            for (int jj = 0; jj < 4; ++jj) {
                pacc[0][jj] += li0 * __expf(acc[0][jj] * SCALEF);
                pacc[1][jj] += li1 * __expf(acc[1][jj] * SCALEF);
                pacc[2][jj] += li2 * __expf(acc[2][jj] * SCALEF);
                pacc[3][jj] += li3 * __expf(acc[3][jj] * SCALEF);
            }
        }
        // causal mask (diagonal tile only) + stage P into smem
#pragma unroll
        for (int ii = 0; ii < 4; ++ii)
#pragma unroll
            for (int jj = 0; jj < 4; ++jj) {
                float pv = pacc[ii][jj];
                if (diag && (tx * 4 + jj) > (ty * 4 + ii)) pv = 0.f;
                ps[(ty * 4 + ii) * 65 + tx * 4 + jj] = pv;
            }
        __syncthreads();

        // O += P @ V   (64x64 @ 64x128)
#pragma unroll 4
        for (int s = 0; s < 64; ++s) {
            float p0 = ps[(ty * 4 + 0) * 65 + s];
            float p1 = ps[(ty * 4 + 1) * 65 + s];
            float p2 = ps[(ty * 4 + 2) * 65 + s];
            float p3 = ps[(ty * 4 + 3) * 65 + s];
            float vr[8];
            *(float4*)(vr)     = *(const float4*)&vs[s * 132 + tx * 8];
            *(float4*)(vr + 4) = *(const float4*)&vs[s * 132 + tx * 8 + 4];
#pragma unroll
            for (int jj = 0; jj < 8; ++jj) {
                o[0][jj] += p0 * vr[jj];
                o[1][jj] += p1 * vr[jj];
                o[2][jj] += p2 * vr[jj];
                o[3][jj] += p3 * vr[jj];
            }
        }
        __syncthreads();
    }

    // fused RMSNorm over the 128 dims owned by this CTA
#pragma unroll
    for (int ii = 0; ii < 4; ++ii) {
        float sq = 0.f;
#pragma unroll
        for (int jj = 0; jj < 8; ++jj) sq += o[ii][jj] * o[ii][jj];
        red[(ty * 4 + ii) * 16 + tx] = sq;
    }
    __syncthreads();
    if (tid < 64) {
        float ssum = 0.f;
#pragma unroll
        for (int u = 0; u < 16; ++u) ssum += red[tid * 16 + u];
        ps[tid] = rsqrtf(ssum * (1.f / 128.f) + 1e-5f);
    }
    __syncthreads();
#pragma unroll
    for (int ii = 0; ii < 4; ++ii) {
        int row = t0 + ty * 4 + ii;
        float rn = ps[ty * 4 + ii];
        float4 o0 = make_float4(o[ii][0] * rn * gm[0], o[ii][1] * rn * gm[1],
                                o[ii][2] * rn * gm[2], o[ii][3] * rn * gm[3]);
        float4 o1 = make_float4(o[ii][4] * rn * gm[4], o[ii][5] * rn * gm[5],
                                o[ii][6] * rn * gm[6], o[ii][7] * rn * gm[7]);
        float* np = g_n + ((size_t)(b * Tt + row)) * Ee + h * 128 + tx * 8;
        *(float4*)(np)     = o0;
        *(float4*)(np + 4) = o1;
    }
}

// ============================================================
extern "C" void kernel_launch(void* const* d_in, const int* in_sizes, int n_in,
                              void* d_out, int out_size)
{
    const float* x      = (const float*)d_in[0];
    const float* cosp   = (const float*)d_in[1];
    const float* sinp   = (const float*)d_in[2];
    const float* q_w    = (const float*)d_in[3];
    const float* k_w    = (const float*)d_in[4];
    const float* v_w    = (const float*)d_in[5];
    const float* out_w  = (const float*)d_in[6];
    const float* raw_w  = (const float*)d_in[7];
    const float* wscale = (const float*)d_in[8];
    const float* gamma  = (const float*)d_in[9];

    float *qb, *kb, *vb, *nb;
    cudaGetSymbolAddress((void**)&qb, g_q);
    cudaGetSymbolAddress((void**)&kb, g_k);
    cudaGetSymbolAddress((void**)&vb, g_v);
    cudaGetSymbolAddress((void**)&nb, g_n);

    cudaFuncSetAttribute(attn_pass1, cudaFuncAttributeMaxDynamicSharedMemorySize, P1_SMEM_BYTES);
    cudaFuncSetAttribute(attn_pass2, cudaFuncAttributeMaxDynamicSharedMemorySize, P2_SMEM_BYTES);

    // projections on tensor cores (rope fused into q,k)
    gemm_tf32<1><<<dim3(Ee / BN, BT / BM), 128>>>(x, q_w, qb, Ee, Ee, cosp, sinp);
    gemm_tf32<1><<<dim3(EKV / BN, BT / BM), 128>>>(x, k_w, kb, EKV, Ee, cosp, sinp);
    gemm_tf32<0><<<dim3(EKV / BN, BT / BM), 128>>>(x, v_w, vb, EKV, Ee, nullptr, nullptr);

    // attention (2-pass, ensemble-combined P, fused RMSNorm)
    dim3 agrid(Tt / 64, Hh, Bb);
    attn_pass1<<<agrid, 256, P1_SMEM_BYTES>>>();
    attn_pass2<<<agrid, 256, P2_SMEM_BYTES>>>(raw_w, wscale, gamma);

    // output projection on tensor cores
    gemm_tf32<0><<<dim3(Ee / BN, BT / BM), 128>>>(nb, out_w, (float*)d_out, Ee, Ee, nullptr, nullptr);
}

// round 3
// speedup vs baseline: 1.9834x; 1.3073x over previous
#include <cuda_runtime.h>
#include <math.h>

// Problem constants
#define Bb 2
#define Tt 2048
#define Ee 2048
#define BT (Bb*Tt)          // 4096
#define Hh 16
#define HKV 4
#define MM 4
#define HD 32
#define EKV 512
#define HALF 16             // HD/2
#define SCALEF 0.17677669529663687f  // 1/sqrt(32)

// -------- scratch buffers (no cudaMalloc allowed) --------
__device__ __align__(128) float g_q[(size_t)BT * Ee];      // q proj + rope
__device__ __align__(128) float g_k[(size_t)BT * EKV];     // k proj + rope
__device__ __align__(128) float g_v[(size_t)BT * EKV];     // v proj
__device__ __align__(128) float g_L[(size_t)Bb * Hh * MM * Tt]; // softmax row sums
__device__ __align__(128) float g_n[(size_t)BT * Ee];      // combined+rmsnorm

// ------------------------------------------------------------
// tf32 helpers
// ------------------------------------------------------------
__device__ __forceinline__ unsigned tf32r(float f)
{
    unsigned u;
    asm("cvt.rna.tf32.f32 %0, %1;\n" : "=r"(u) : "f"(f));
    return u;
}
__device__ __forceinline__ float2 tf32split(float f)
{
    unsigned h = tf32r(f);
    float hf = __uint_as_float(h);
    unsigned l = tf32r(f - hf);
    return make_float2(hf, __uint_as_float(l));
}
__device__ __forceinline__ void mma_tf32(float c[4], const unsigned a[4], const unsigned b[2])
{
    asm volatile(
        "mma.sync.aligned.m16n8k8.row.col.f32.tf32.tf32.f32 "
        "{%0,%1,%2,%3}, {%4,%5,%6,%7}, {%8,%9}, {%0,%1,%2,%3};\n"
        : "+f"(c[0]), "+f"(c[1]), "+f"(c[2]), "+f"(c[3])
        : "r"(a[0]), "r"(a[1]), "r"(a[2]), "r"(a[3]), "r"(b[0]), "r"(b[1]));
}

// ============================================================
// tf32 tensor-core GEMM: C[m,n] = sum_k A[m,k] * W[n,k]
// (unchanged from R2 — validated)
// ============================================================
#define BM 128
#define BN 128
#define BKt 16
#define STRIDE 20

__device__ __forceinline__ void cp_issue_tile(
    const float* __restrict__ A, const float* __restrict__ W,
    int K, int m0, int n0, int k0,
    float* __restrict__ asb, float* __restrict__ bsb, int tid)
{
#pragma unroll
    for (int i = 0; i < 4; ++i) {
        int idx = tid + i * 128;
        int row = idx >> 2;
        int kq  = (idx & 3) << 2;
        const float* gA = A + (size_t)(m0 + row) * K + k0 + kq;
        unsigned sA = (unsigned)__cvta_generic_to_shared(asb + row * STRIDE + kq);
        asm volatile("cp.async.ca.shared.global [%0], [%1], 16;\n" :: "r"(sA), "l"(gA));
        const float* gW = W + (size_t)(n0 + row) * K + k0 + kq;
        unsigned sB = (unsigned)__cvta_generic_to_shared(bsb + row * STRIDE + kq);
        asm volatile("cp.async.ca.shared.global [%0], [%1], 16;\n" :: "r"(sB), "l"(gW));
    }
    asm volatile("cp.async.commit_group;\n");
}

template<int ROPE>
__global__ __launch_bounds__(128)
void gemm_tf32(const float* __restrict__ A, const float* __restrict__ W,
               float* __restrict__ C, int N, int K,
               const float* __restrict__ cosp, const float* __restrict__ sinp)
{
    __shared__ float As[2][BM * STRIDE];
    __shared__ float Bs[2][BN * STRIDE];

    const int tid  = threadIdx.x;
    const int lane = tid & 31;
    const int warp = tid >> 5;
    const int g    = lane >> 2;
    const int tig  = lane & 3;
    const int wm   = warp >> 1;
    const int wn   = warp & 1;
    const int m0 = blockIdx.y * BM;
    const int n0 = blockIdx.x * BN;

    float c[4][8][4];
#pragma unroll
    for (int mt = 0; mt < 4; ++mt)
#pragma unroll
        for (int nt = 0; nt < 8; ++nt)
#pragma unroll
            for (int r = 0; r < 4; ++r) c[mt][nt][r] = 0.f;

    cp_issue_tile(A, W, K, m0, n0, 0, As[0], Bs[0], tid);

    const int NT = K / BKt;
    for (int kt = 0; kt < NT; ++kt) {
        if (kt + 1 < NT)
            cp_issue_tile(A, W, K, m0, n0, (kt + 1) * BKt,
                          As[(kt + 1) & 1], Bs[(kt + 1) & 1], tid);
        else
            asm volatile("cp.async.commit_group;\n");
        asm volatile("cp.async.wait_group 1;\n");
        __syncthreads();

        const float* as = &As[kt & 1][(wm * 64 + g) * STRIDE + tig];
        const float* bs = &Bs[kt & 1][(wn * 64 + g) * STRIDE + tig];

#pragma unroll
        for (int ks = 0; ks < BKt; ks += 8) {
            unsigned a[4][4], b[8][2];
#pragma unroll
            for (int mt = 0; mt < 4; ++mt) {
                a[mt][0] = tf32r(as[(mt * 16    ) * STRIDE + ks    ]);
                a[mt][1] = tf32r(as[(mt * 16 + 8) * STRIDE + ks    ]);
                a[mt][2] = tf32r(as[(mt * 16    ) * STRIDE + ks + 4]);
                a[mt][3] = tf32r(as[(mt * 16 + 8) * STRIDE + ks + 4]);
            }
#pragma unroll
            for (int nt = 0; nt < 8; ++nt) {
                b[nt][0] = tf32r(bs[(nt * 8) * STRIDE + ks    ]);
                b[nt][1] = tf32r(bs[(nt * 8) * STRIDE + ks + 4]);
            }
#pragma unroll
            for (int mt = 0; mt < 4; ++mt)
#pragma unroll
                for (int nt = 0; nt < 8; ++nt)
                    mma_tf32(c[mt][nt], a[mt], b[nt]);
        }
        __syncthreads();
    }

#pragma unroll
    for (int mt = 0; mt < 4; ++mt) {
        int mA = m0 + wm * 64 + mt * 16 + g;
        int mB = mA + 8;
#pragma unroll
        for (int nt = 0; nt < 8; ++nt) {
            int n = n0 + wn * 64 + nt * 8 + tig * 2;
            float v0 = c[mt][nt][0], v1 = c[mt][nt][1];
            float v2 = c[mt][nt][2], v3 = c[mt][nt][3];
            if (ROPE) {
                int p = (n & 31) >> 1;
                int tA = mA & (Tt - 1), tB = mB & (Tt - 1);
                float cA = cosp[tA * HALF + p], snA = sinp[tA * HALF + p];
                float cB = cosp[tB * HALF + p], snB = sinp[tB * HALF + p];
                float e = v0, o = v1;
                v0 = e * cA - o * snA; v1 = e * snA + o * cA;
                e = v2; o = v3;
                v2 = e * cB - o * snB; v3 = e * snB + o * cB;
            }
            *(float2*)(C + (size_t)mA * N + n) = make_float2(v0, v1);
            *(float2*)(C + (size_t)mB * N + n) = make_float2(v2, v3);
        }
    }
}

// ============================================================
// mma-based attention, 2-pass. CTA: 128 q-rows, 64 s-cols/iter,
// 256 threads = 8 warps x 16 q-rows.
// QK^T: 3xTF32 (Q split on-the-fly, K pre-split in smem float2{hi,lo}).
// PV:   3xTF32 (P split in regs after shuffle, V pre-split in smem).
// ============================================================
#define QS_STR 132       // floats
#define KS_STR 132       // float2 units

// compute S (16x64) for one member with 3xTF32 into sc[8][4]
__device__ __forceinline__ void qk_member(const float* __restrict__ qb,
                                          const float2* __restrict__ kb,
                                          float sc[8][4])
{
#pragma unroll
    for (int kc = 0; kc < 4; ++kc) {
        float f0 = qb[kc * 8];
        float f1 = qb[kc * 8 + 8 * QS_STR];
        float f2 = qb[kc * 8 + 4];
        float f3 = qb[kc * 8 + 4 + 8 * QS_STR];
        float2 s0 = tf32split(f0), s1 = tf32split(f1), s2 = tf32split(f2), s3 = tf32split(f3);
        unsigned ah[4] = {__float_as_uint(s0.x), __float_as_uint(s1.x),
                          __float_as_uint(s2.x), __float_as_uint(s3.x)};
        unsigned al[4] = {__float_as_uint(s0.y), __float_as_uint(s1.y),
                          __float_as_uint(s2.y), __float_as_uint(s3.y)};
#pragma unroll
        for (int nt = 0; nt < 8; ++nt) {
            float2 b0 = kb[(nt * 8) * KS_STR + kc * 8];
            float2 b1 = kb[(nt * 8) * KS_STR + kc * 8 + 4];
            unsigned bh[2] = {__float_as_uint(b0.x), __float_as_uint(b1.x)};
            unsigned bl[2] = {__float_as_uint(b0.y), __float_as_uint(b1.y)};
            mma_tf32(sc[nt], ah, bh);
            mma_tf32(sc[nt], al, bh);
            mma_tf32(sc[nt], ah, bl);
        }
    }
}

__device__ __forceinline__ void load_q_tile(const float* __restrict__ gq,
                                            float* __restrict__ qs, int tid)
{
#pragma unroll
    for (int it = 0; it < 16; ++it) {
        int idx = tid + it * 256;
        int row = idx >> 5;
        int cq  = (idx & 31) << 2;
        float4 a = *(const float4*)(gq + (size_t)row * Ee + cq);
        float* d = qs + row * QS_STR + cq;
        d[0] = a.x; d[1] = a.y; d[2] = a.z; d[3] = a.w;
    }
}

__device__ __forceinline__ void load_kv_split(const float* __restrict__ gsrc,
                                              float2* __restrict__ dst, int tid)
{
#pragma unroll
    for (int it = 0; it < 8; ++it) {
        int idx = tid + it * 256;
        int row = idx >> 5;
        int cq  = (idx & 31) << 2;
        float4 a = *(const float4*)(gsrc + (size_t)row * EKV + cq);
        float2* d = dst + row * KS_STR + cq;
        d[0] = tf32split(a.x); d[1] = tf32split(a.y);
        d[2] = tf32split(a.z); d[3] = tf32split(a.w);
    }
}

// ---------------- pass 1: softmax denominators ----------------
#define P1_SMEM_BYTES ((128*QS_STR + 64*KS_STR*2) * 4)

__global__ __launch_bounds__(256, 1)
void attn_pass1()
{
    extern __shared__ float sm[];
    float*  qs  = sm;
    float2* ks2 = (float2*)(sm + 128 * QS_STR);

    const int tid = threadIdx.x;
    const int lane = tid & 31, w = tid >> 5;
    const int g = lane >> 2, tig = lane & 3;
    const int qt = blockIdx.x, h = blockIdx.y, b = blockIdx.z;
    const int kvg = h >> 2;
    const int t0 = qt * 128;
    const int row0 = t0 + w * 16 + g;

    load_q_tile(g_q + ((size_t)(b * Tt + t0)) * Ee + h * 128, qs, tid);

    float rs[MM][2];
#pragma unroll
    for (int i = 0; i < MM; ++i) { rs[i][0] = 0.f; rs[i][1] = 0.f; }

    const int nst = 2 * qt + 2;
    for (int st = 0; st < nst; ++st) {
        int s0 = st * 64;
        load_kv_split(g_k + ((size_t)(b * Tt + s0)) * EKV + kvg * 128, ks2, tid);
        __syncthreads();

        if (s0 <= t0 + w * 16 + 15) {
            const bool full = (s0 + 63 <= t0 + w * 16);
#pragma unroll
            for (int i = 0; i < MM; ++i) {
                float sc[8][4];
#pragma unroll
                for (int nt = 0; nt < 8; ++nt)
#pragma unroll
                    for (int r = 0; r < 4; ++r) sc[nt][r] = 0.f;
                qk_member(qs + (w * 16 + g) * QS_STR + i * HD + tig,
                          ks2 + g * KS_STR + i * HD + tig, sc);
                if (full) {
#pragma unroll
                    for (int nt = 0; nt < 8; ++nt) {
                        rs[i][0] += __expf(sc[nt][0] * SCALEF) + __expf(sc[nt][1] * SCALEF);
                        rs[i][1] += __expf(sc[nt][2] * SCALEF) + __expf(sc[nt][3] * SCALEF);
                    }
                } else {
#pragma unroll
                    for (int nt = 0; nt < 8; ++nt) {
                        int col = s0 + nt * 8 + tig * 2;
                        if (col     <= row0)     rs[i][0] += __expf(sc[nt][0] * SCALEF);
                        if (col + 1 <= row0)     rs[i][0] += __expf(sc[nt][1] * SCALEF);
                        if (col     <= row0 + 8) rs[i][1] += __expf(sc[nt][2] * SCALEF);
                        if (col + 1 <= row0 + 8) rs[i][1] += __expf(sc[nt][3] * SCALEF);
                    }
                }
            }
        }
        __syncthreads();
    }

#pragma unroll
    for (int i = 0; i < MM; ++i) {
        rs[i][0] += __shfl_xor_sync(0xffffffffu, rs[i][0], 1);
        rs[i][0] += __shfl_xor_sync(0xffffffffu, rs[i][0], 2);
        rs[i][1] += __shfl_xor_sync(0xffffffffu, rs[i][1], 1);
        rs[i][1] += __shfl_xor_sync(0xffffffffu, rs[i][1], 2);
        if (tig == 0) {
            size_t base = (((size_t)b * Hh + h) * MM + i) * Tt;
            g_L[base + row0]     = rs[i][0];
            g_L[base + row0 + 8] = rs[i][1];
        }
    }
}

// ---------------- pass 2: combined P @ V + fused RMSNorm ----------------
#define P2_QS_F   (128*QS_STR)
#define P2_KS_F   (64*KS_STR*2)
#define P2_VS_F   (64*KS_STR*2)
#define P2_LINV_F (MM*128)
#define P2_GM_F   128
#define P2_SMEM_BYTES ((P2_QS_F + P2_KS_F + P2_VS_F + P2_LINV_F + P2_GM_F) * 4)

__global__ __launch_bounds__(256, 1)
void attn_pass2(const float* __restrict__ raw_w,
                const float* __restrict__ wscale,
                const float* __restrict__ gamma)
{
    extern __shared__ float sm[];
    float*  qs   = sm;
    float2* ks2  = (float2*)(sm + P2_QS_F);
    float2* vs2  = (float2*)(sm + P2_QS_F + P2_KS_F);
    float*  linv = sm + P2_QS_F + P2_KS_F + P2_VS_F;
    float*  gms  = linv + P2_LINV_F;

    const int tid = threadIdx.x;
    const int lane = tid & 31, w = tid >> 5;
    const int g = lane >> 2, tig = lane & 3;
    const int qt = blockIdx.x, h = blockIdx.y, b = blockIdx.z;
    const int kvg = h >> 2;
    const int t0 = qt * 128;
    const int row0 = t0 + w * 16 + g;

    if (tid < 128) {
        float ws = wscale[0];
#pragma unroll
        for (int i = 0; i < MM; ++i) {
            float wi = tanhf(raw_w[i]) * ws;
            float l = g_L[(((size_t)b * Hh + h) * MM + i) * Tt + t0 + tid];
            linv[i * 128 + tid] = wi / l;
        }
        gms[tid] = gamma[tid];
    }
    load_q_tile(g_q + ((size_t)(b * Tt + t0)) * Ee + h * 128, qs, tid);

    float o[16][4];
#pragma unroll
    for (int nt = 0; nt < 16; ++nt)
#pragma unroll
        for (int r = 0; r < 4; ++r) o[nt][r] = 0.f;

    const int nst = 2 * qt + 2;
    for (int st = 0; st < nst; ++st) {
        int s0 = st * 64;
        load_kv_split(g_k + ((size_t)(b * Tt + s0)) * EKV + kvg * 128, ks2, tid);
        load_kv_split(g_v + ((size_t)(b * Tt + s0)) * EKV + kvg * 128, vs2, tid);
        __syncthreads();

        if (s0 <= t0 + w * 16 + 15) {
            const bool full = (s0 + 63 <= t0 + w * 16);
            float p[8][4];
#pragma unroll
            for (int nt = 0; nt < 8; ++nt)
#pragma unroll
                for (int r = 0; r < 4; ++r) p[nt][r] = 0.f;

#pragma unroll
            for (int i = 0; i < MM; ++i) {
                float sc[8][4];
#pragma unroll
                for (int nt = 0; nt < 8; ++nt)
#pragma unroll
                    for (int r = 0; r < 4; ++r) sc[nt][r] = 0.f;
                qk_member(qs + (w * 16 + g) * QS_STR + i * HD + tig,
                          ks2 + g * KS_STR + i * HD + tig, sc);
                float l0 = linv[i * 128 + w * 16 + g];
                float l1 = linv[i * 128 + w * 16 + g + 8];
                if (full) {
#pragma unroll
                    for (int nt = 0; nt < 8; ++nt) {
                        p[nt][0] += l0 * __expf(sc[nt][0] * SCALEF);
                        p[nt][1] += l0 * __expf(sc[nt][1] * SCALEF);
                        p[nt][2] += l1 * __expf(sc[nt][2] * SCALEF);
                        p[nt][3] += l1 * __expf(sc[nt][3] * SCALEF);
                    }
                } else {
#pragma unroll
                    for (int nt = 0; nt < 8; ++nt) {
                        int col = s0 + nt * 8 + tig * 2;
                        if (col     <= row0)     p[nt][0] += l0 * __expf(sc[nt][0] * SCALEF);
                        if (col + 1 <= row0)     p[nt][1] += l0 * __expf(sc[nt][1] * SCALEF);
                        if (col     <= row0 + 8) p[nt][2] += l1 * __expf(sc[nt][2] * SCALEF);
                        if (col + 1 <= row0 + 8) p[nt][3] += l1 * __expf(sc[nt][3] * SCALEF);
                    }
                }
            }

            // PV: for each 8-wide k-chunk, rearrange P acc-layout -> A-frag via shfl
            const int srcA = (lane & ~3) | (tig >> 1);
            const int srcB = srcA + 2;
#pragma unroll
            for (int kc = 0; kc < 8; ++kc) {
                float c0 = p[kc][0], c1 = p[kc][1], c2 = p[kc][2], c3 = p[kc][3];
                float t0a = __shfl_sync(0xffffffffu, c0, srcA);
                float t1a = __shfl_sync(0xffffffffu, c1, srcA);
                float t0b = __shfl_sync(0xffffffffu, c0, srcB);
                float t1b = __shfl_sync(0xffffffffu, c1, srcB);
                float t2a = __shfl_sync(0xffffffffu, c2, srcA);
                float t3a = __shfl_sync(0xffffffffu, c3, srcA);
                float t2b = __shfl_sync(0xffffffffu, c2, srcB);
                float t3b = __shfl_sync(0xffffffffu, c3, srcB);
                bool odd = (tig & 1);
                float a0f = odd ? t1a : t0a;   // P[g][tig]
                float a1f = odd ? t3a : t2a;   // P[g+8][tig]
                float a2f = odd ? t1b : t0b;   // P[g][tig+4]
                float a3f = odd ? t3b : t2b;   // P[g+8][tig+4]
                float2 sp0 = tf32split(a0f), sp1 = tf32split(a1f);
                float2 sp2 = tf32split(a2f), sp3 = tf32split(a3f);
                unsigned pah[4] = {__float_as_uint(sp0.x), __float_as_uint(sp1.x),
                                   __float_as_uint(sp2.x), __float_as_uint(sp3.x)};
                unsigned pal[4] = {__float_as_uint(sp0.y), __float_as_uint(sp1.y),
                                   __float_as_uint(sp2.y), __float_as_uint(sp3.y)};
                const float2* vb  = vs2 + (kc * 8 + tig) * KS_STR + g;
                const float2* vb4 = vs2 + (kc * 8 + tig + 4) * KS_STR + g;
#pragma unroll
                for (int nt = 0; nt < 16; ++nt) {
                    float2 bh = vb[nt * 8];
                    float2 b4 = vb4[nt * 8];
                    unsigned bhh[2] = {__float_as_uint(bh.x), __float_as_uint(b4.x)};
                    unsigned bll[2] = {__float_as_uint(bh.y), __float_as_uint(b4.y)};
                    mma_tf32(o[nt], pah, bhh);
                    mma_tf32(o[nt], pal, bhh);
                    mma_tf32(o[nt], pah, bll);
                }
            }
        }
        __syncthreads();
    }

    // fused RMSNorm over the 128 dims (quad butterfly, no smem)
    float sq0 = 0.f, sq1 = 0.f;
#pragma unroll
    for (int nt = 0; nt < 16; ++nt) {
        sq0 += o[nt][0] * o[nt][0] + o[nt][1] * o[nt][1];
        sq1 += o[nt][2] * o[nt][2] + o[nt][3] * o[nt][3];
    }
    sq0 += __shfl_xor_sync(0xffffffffu, sq0, 1);
    sq0 += __shfl_xor_sync(0xffffffffu, sq0, 2);
    sq1 += __shfl_xor_sync(0xffffffffu, sq1, 1);
    sq1 += __shfl_xor_sync(0xffffffffu, sq1, 2);
    float rn0 = rsqrtf(sq0 * (1.f / 128.f) + 1e-5f);
    float rn1 = rsqrtf(sq1 * (1.f / 128.f) + 1e-5f);

#pragma unroll
    for (int nt = 0; nt < 16; ++nt) {
        float g0 = gms[nt * 8 + tig * 2];
        float g1 = gms[nt * 8 + tig * 2 + 1];
        float* p0 = g_n + ((size_t)(b * Tt + row0)) * Ee + h * 128 + nt * 8 + tig * 2;
        float* p1 = g_n + ((size_t)(b * Tt + row0 + 8)) * Ee + h * 128 + nt * 8 + tig * 2;
        *(float2*)p0 = make_float2(o[nt][0] * rn0 * g0, o[nt][1] * rn0 * g1);
        *(float2*)p1 = make_float2(o[nt][2] * rn1 * g0, o[nt][3] * rn1 * g1);
    }
}

// ============================================================
extern "C" void kernel_launch(void* const* d_in, const int* in_sizes, int n_in,
                              void* d_out, int out_size)
{
    const float* x      = (const float*)d_in[0];
    const float* cosp   = (const float*)d_in[1];
    const float* sinp   = (const float*)d_in[2];
    const float* q_w    = (const float*)d_in[3];
    const float* k_w    = (const float*)d_in[4];
    const float* v_w    = (const float*)d_in[5];
    const float* out_w  = (const float*)d_in[6];
    const float* raw_w  = (const float*)d_in[7];
    const float* wscale = (const float*)d_in[8];
    const float* gamma  = (const float*)d_in[9];

    float *qb, *kb, *vb, *nb;
    cudaGetSymbolAddress((void**)&qb, g_q);
    cudaGetSymbolAddress((void**)&kb, g_k);
    cudaGetSymbolAddress((void**)&vb, g_v);
    cudaGetSymbolAddress((void**)&nb, g_n);

    cudaFuncSetAttribute(attn_pass1, cudaFuncAttributeMaxDynamicSharedMemorySize, P1_SMEM_BYTES);
    cudaFuncSetAttribute(attn_pass2, cudaFuncAttributeMaxDynamicSharedMemorySize, P2_SMEM_BYTES);

    // projections on tensor cores (rope fused into q,k)
    gemm_tf32<1><<<dim3(Ee / BN, BT / BM), 128>>>(x, q_w, qb, Ee, Ee, cosp, sinp);
    gemm_tf32<1><<<dim3(EKV / BN, BT / BM), 128>>>(x, k_w, kb, EKV, Ee, cosp, sinp);
    gemm_tf32<0><<<dim3(EKV / BN, BT / BM), 128>>>(x, v_w, vb, EKV, Ee, nullptr, nullptr);

    // attention (2-pass, 3xTF32 mma, fused RMSNorm)
    dim3 agrid(Tt / 128, Hh, Bb);
    attn_pass1<<<agrid, 256, P1_SMEM_BYTES>>>();
    attn_pass2<<<agrid, 256, P2_SMEM_BYTES>>>(raw_w, wscale, gamma);

    // output projection on tensor cores
    gemm_tf32<0><<<dim3(Ee / BN, BT / BM), 128>>>(nb, out_w, (float*)d_out, Ee, Ee, nullptr, nullptr);
}

// round 4
// speedup vs baseline: 2.0683x; 1.0428x over previous
#include <cuda_runtime.h>
#include <math.h>

// Problem constants
#define Bb 2
#define Tt 2048
#define Ee 2048
#define BT (Bb*Tt)          // 4096
#define Hh 16
#define HKV 4
#define MM 4
#define HD 32
#define EKV 512
#define HALF 16             // HD/2
#define SCALEF 0.17677669529663687f  // 1/sqrt(32)

// -------- scratch buffers (no cudaMalloc allowed) --------
__device__ __align__(128) float g_q[(size_t)BT * Ee];      // q proj + rope
__device__ __align__(128) float g_k[(size_t)BT * EKV];     // k proj + rope
__device__ __align__(128) float g_v[(size_t)BT * EKV];     // v proj
__device__ __align__(128) float g_L[(size_t)Bb * Hh * MM * Tt]; // softmax row sums
__device__ __align__(128) float g_n[(size_t)BT * Ee];      // combined+rmsnorm

// ------------------------------------------------------------
// tf32 helpers
// ------------------------------------------------------------
__device__ __forceinline__ unsigned tf32r(float f)
{
    unsigned u;
    asm("cvt.rna.tf32.f32 %0, %1;\n" : "=r"(u) : "f"(f));
    return u;
}
__device__ __forceinline__ float2 tf32split(float f)
{
    unsigned h = tf32r(f);
    float hf = __uint_as_float(h);
    unsigned l = tf32r(f - hf);
    return make_float2(hf, __uint_as_float(l));
}
__device__ __forceinline__ void mma_tf32(float c[4], const unsigned a[4], const unsigned b[2])
{
    asm volatile(
        "mma.sync.aligned.m16n8k8.row.col.f32.tf32.tf32.f32 "
        "{%0,%1,%2,%3}, {%4,%5,%6,%7}, {%8,%9}, {%0,%1,%2,%3};\n"
        : "+f"(c[0]), "+f"(c[1]), "+f"(c[2]), "+f"(c[3])
        : "r"(a[0]), "r"(a[1]), "r"(a[2]), "r"(a[3]), "r"(b[0]), "r"(b[1]));
}
__device__ __forceinline__ void ldsm4(unsigned r[4], const float* p)
{
    unsigned a = (unsigned)__cvta_generic_to_shared(p);
    asm volatile("ldmatrix.sync.aligned.m8n8.x4.shared.b16 {%0,%1,%2,%3}, [%4];"
        : "=r"(r[0]), "=r"(r[1]), "=r"(r[2]), "=r"(r[3]) : "r"(a));
}

// ============================================================
// tf32 tensor-core GEMM v2: C[m,n] = sum_k A[m,k] * W[n,k]
// 256 threads = 8 warps (4 row x 2 col), warp tile 32x64.
// BK=32, ldmatrix fragment loads, 2-stage cp.async, 2 CTA/SM.
// ============================================================
#define GBK 32
#define GSTR 36
#define G_SMEM_BYTES (4 * 128 * GSTR * 4)   // As[2] + Bs[2]

__device__ __forceinline__ void g2_issue(
    const float* __restrict__ A, const float* __restrict__ W,
    int K, int m0, int n0, int k0,
    float* __restrict__ asb, float* __restrict__ bsb, int tid)
{
#pragma unroll
    for (int i = 0; i < 4; ++i) {
        int idx = tid + i * 256;
        int row = idx >> 3;
        int c4  = (idx & 7) << 2;
        const float* gA = A + (size_t)(m0 + row) * K + k0 + c4;
        unsigned sA = (unsigned)__cvta_generic_to_shared(asb + row * GSTR + c4);
        asm volatile("cp.async.ca.shared.global [%0], [%1], 16;\n" :: "r"(sA), "l"(gA));
        const float* gW = W + (size_t)(n0 + row) * K + k0 + c4;
        unsigned sB = (unsigned)__cvta_generic_to_shared(bsb + row * GSTR + c4);
        asm volatile("cp.async.ca.shared.global [%0], [%1], 16;\n" :: "r"(sB), "l"(gW));
    }
    asm volatile("cp.async.commit_group;\n");
}

template<int ROPE>
__global__ __launch_bounds__(256, 2)
void gemm_tf32_v2(const float* __restrict__ A, const float* __restrict__ W,
                  float* __restrict__ C, int N, int K,
                  const float* __restrict__ cosp, const float* __restrict__ sinp)
{
    extern __shared__ float gsm[];
    float* As0 = gsm;
    float* As1 = gsm + 128 * GSTR;
    float* Bs0 = gsm + 2 * 128 * GSTR;
    float* Bs1 = gsm + 3 * 128 * GSTR;

    const int tid  = threadIdx.x;
    const int lane = tid & 31;
    const int warp = tid >> 5;
    const int g    = lane >> 2;
    const int tig  = lane & 3;
    const int wm   = warp >> 1;   // 0..3
    const int wn   = warp & 1;    // 0..1
    const int m0 = blockIdx.y * 128;
    const int n0 = blockIdx.x * 128;

    // per-lane ldmatrix row/col offsets
    const int a_row = lane & 15;
    const int a_k4  = (lane >> 4) << 2;                 // 0 or 4
    const int b_row = (lane & 7) + ((lane >> 4) << 3);  // 0-7 / 8-15
    const int b_k4  = ((lane >> 3) & 1) << 2;           // 0 or 4

    float c[2][8][4];
#pragma unroll
    for (int mt = 0; mt < 2; ++mt)
#pragma unroll
        for (int nt = 0; nt < 8; ++nt)
#pragma unroll
            for (int r = 0; r < 4; ++r) c[mt][nt][r] = 0.f;

    g2_issue(A, W, K, m0, n0, 0, As0, Bs0, tid);

    const int NT = K / GBK;
    for (int kt = 0; kt < NT; ++kt) {
        if (kt + 1 < NT)
            g2_issue(A, W, K, m0, n0, (kt + 1) * GBK,
                     ((kt + 1) & 1) ? As1 : As0, ((kt + 1) & 1) ? Bs1 : Bs0, tid);
        else
            asm volatile("cp.async.commit_group;\n");
        asm volatile("cp.async.wait_group 1;\n");
        __syncthreads();

        const float* ab = ((kt & 1) ? As1 : As0) + (wm * 32) * GSTR;
        const float* bb = ((kt & 1) ? Bs1 : Bs0) + (wn * 64) * GSTR;

#pragma unroll
        for (int ks = 0; ks < GBK; ks += 8) {
            unsigned a[2][4], b[8][2];
#pragma unroll
            for (int mt = 0; mt < 2; ++mt) {
                unsigned r[4];
                ldsm4(r, ab + (mt * 16 + a_row) * GSTR + ks + a_k4);
#pragma unroll
                for (int j = 0; j < 4; ++j) a[mt][j] = tf32r(__uint_as_float(r[j]));
            }
#pragma unroll
            for (int j = 0; j < 4; ++j) {
                unsigned r[4];
                ldsm4(r, bb + (j * 16 + b_row) * GSTR + ks + b_k4);
                b[2 * j][0]     = tf32r(__uint_as_float(r[0]));
                b[2 * j][1]     = tf32r(__uint_as_float(r[1]));
                b[2 * j + 1][0] = tf32r(__uint_as_float(r[2]));
                b[2 * j + 1][1] = tf32r(__uint_as_float(r[3]));
            }
#pragma unroll
            for (int mt = 0; mt < 2; ++mt)
#pragma unroll
                for (int nt = 0; nt < 8; ++nt)
                    mma_tf32(c[mt][nt], a[mt], b[nt]);
        }
        __syncthreads();
    }

#pragma unroll
    for (int mt = 0; mt < 2; ++mt) {
        int mA = m0 + wm * 32 + mt * 16 + g;
        int mB = mA + 8;
#pragma unroll
        for (int nt = 0; nt < 8; ++nt) {
            int n = n0 + wn * 64 + nt * 8 + tig * 2;
            float v0 = c[mt][nt][0], v1 = c[mt][nt][1];
            float v2 = c[mt][nt][2], v3 = c[mt][nt][3];
            if (ROPE) {
                int p = (n & 31) >> 1;
                int tA = mA & (Tt - 1), tB = mB & (Tt - 1);
                float cA = cosp[tA * HALF + p], snA = sinp[tA * HALF + p];
                float cB = cosp[tB * HALF + p], snB = sinp[tB * HALF + p];
                float e = v0, o = v1;
                v0 = e * cA - o * snA; v1 = e * snA + o * cA;
                e = v2; o = v3;
                v2 = e * cB - o * snB; v3 = e * snB + o * cB;
            }
            *(float2*)(C + (size_t)mA * N + n) = make_float2(v0, v1);
            *(float2*)(C + (size_t)mB * N + n) = make_float2(v2, v3);
        }
    }
}

// ============================================================
// mma-based attention, 2-pass. CTA: 128 q-rows, 64 s-cols/iter,
// 256 threads = 8 warps x 16 q-rows. 3xTF32 QK and PV.
// Register prefetch of K/V tiles overlaps LDG with mma phases.
// ============================================================
#define QS_STR 132       // floats
#define KS_STR 132       // float2 units

__device__ __forceinline__ void qk_member(const float* __restrict__ qb,
                                          const float2* __restrict__ kb,
                                          float sc[8][4])
{
#pragma unroll
    for (int kc = 0; kc < 4; ++kc) {
        float f0 = qb[kc * 8];
        float f1 = qb[kc * 8 + 8 * QS_STR];
        float f2 = qb[kc * 8 + 4];
        float f3 = qb[kc * 8 + 4 + 8 * QS_STR];
        float2 s0 = tf32split(f0), s1 = tf32split(f1), s2 = tf32split(f2), s3 = tf32split(f3);
        unsigned ah[4] = {__float_as_uint(s0.x), __float_as_uint(s1.x),
                          __float_as_uint(s2.x), __float_as_uint(s3.x)};
        unsigned al[4] = {__float_as_uint(s0.y), __float_as_uint(s1.y),
                          __float_as_uint(s2.y), __float_as_uint(s3.y)};
#pragma unroll
        for (int nt = 0; nt < 8; ++nt) {
            float2 b0 = kb[(nt * 8) * KS_STR + kc * 8];
            float2 b1 = kb[(nt * 8) * KS_STR + kc * 8 + 4];
            unsigned bh[2] = {__float_as_uint(b0.x), __float_as_uint(b1.x)};
            unsigned bl[2] = {__float_as_uint(b0.y), __float_as_uint(b1.y)};
            mma_tf32(sc[nt], ah, bh);
            mma_tf32(sc[nt], al, bh);
            mma_tf32(sc[nt], ah, bl);
        }
    }
}

__device__ __forceinline__ void load_q_tile(const float* __restrict__ gq,
                                            float* __restrict__ qs, int tid)
{
#pragma unroll
    for (int it = 0; it < 16; ++it) {
        int idx = tid + it * 256;
        int row = idx >> 5;
        int cq  = (idx & 31) << 2;
        float4 a = *(const float4*)(gq + (size_t)row * Ee + cq);
        float* d = qs + row * QS_STR + cq;
        d[0] = a.x; d[1] = a.y; d[2] = a.z; d[3] = a.w;
    }
}

// prefetch one 64x128 tile into registers
__device__ __forceinline__ void ldg_tile(const float* __restrict__ gsrc,
                                         float4* __restrict__ pf, int tid)
{
#pragma unroll
    for (int it = 0; it < 8; ++it) {
        int idx = tid + it * 256;
        int row = idx >> 5;
        int cq  = (idx & 31) << 2;
        pf[it] = *(const float4*)(gsrc + (size_t)row * EKV + cq);
    }
}

// split registers into {hi,lo} float2 smem
__device__ __forceinline__ void sts_split(const float4* __restrict__ pf,
                                          float2* __restrict__ dst, int tid)
{
#pragma unroll
    for (int it = 0; it < 8; ++it) {
        int idx = tid + it * 256;
        int row = idx >> 5;
        int cq  = (idx & 31) << 2;
        float2* d = dst + row * KS_STR + cq;
        d[0] = tf32split(pf[it].x); d[1] = tf32split(pf[it].y);
        d[2] = tf32split(pf[it].z); d[3] = tf32split(pf[it].w);
    }
}

// ---------------- pass 1: softmax denominators ----------------
#define P1_SMEM_BYTES ((128*QS_STR + 64*KS_STR*2) * 4)

__global__ __launch_bounds__(256, 1)
void attn_pass1()
{
    extern __shared__ float sm[];
    float*  qs  = sm;
    float2* ks2 = (float2*)(sm + 128 * QS_STR);

    const int tid = threadIdx.x;
    const int lane = tid & 31, w = tid >> 5;
    const int g = lane >> 2, tig = lane & 3;
    const int qt = blockIdx.x, h = blockIdx.y, b = blockIdx.z;
    const int kvg = h >> 2;
    const int t0 = qt * 128;
    const int row0 = t0 + w * 16 + g;

    load_q_tile(g_q + ((size_t)(b * Tt + t0)) * Ee + h * 128, qs, tid);

    float rs[MM][2];
#pragma unroll
    for (int i = 0; i < MM; ++i) { rs[i][0] = 0.f; rs[i][1] = 0.f; }

    const int nst = 2 * qt + 2;
    float4 pf[8];
    ldg_tile(g_k + ((size_t)(b * Tt)) * EKV + kvg * 128, pf, tid);

    for (int st = 0; st < nst; ++st) {
        int s0 = st * 64;
        sts_split(pf, ks2, tid);
        if (st + 1 < nst)
            ldg_tile(g_k + ((size_t)(b * Tt + s0 + 64)) * EKV + kvg * 128, pf, tid);
        __syncthreads();

        if (s0 <= t0 + w * 16 + 15) {
            const bool full = (s0 + 63 <= t0 + w * 16);
#pragma unroll
            for (int i = 0; i < MM; ++i) {
                float sc[8][4];
#pragma unroll
                for (int nt = 0; nt < 8; ++nt)
#pragma unroll
                    for (int r = 0; r < 4; ++r) sc[nt][r] = 0.f;
                qk_member(qs + (w * 16 + g) * QS_STR + i * HD + tig,
                          ks2 + g * KS_STR + i * HD + tig, sc);
                if (full) {
#pragma unroll
                    for (int nt = 0; nt < 8; ++nt) {
                        rs[i][0] += __expf(sc[nt][0] * SCALEF) + __expf(sc[nt][1] * SCALEF);
                        rs[i][1] += __expf(sc[nt][2] * SCALEF) + __expf(sc[nt][3] * SCALEF);
                    }
                } else {
#pragma unroll
                    for (int nt = 0; nt < 8; ++nt) {
                        int col = s0 + nt * 8 + tig * 2;
                        if (col     <= row0)     rs[i][0] += __expf(sc[nt][0] * SCALEF);
                        if (col + 1 <= row0)     rs[i][0] += __expf(sc[nt][1] * SCALEF);
                        if (col     <= row0 + 8) rs[i][1] += __expf(sc[nt][2] * SCALEF);
                        if (col + 1 <= row0 + 8) rs[i][1] += __expf(sc[nt][3] * SCALEF);
                    }
                }
            }
        }
        __syncthreads();
    }

#pragma unroll
    for (int i = 0; i < MM; ++i) {
        rs[i][0] += __shfl_xor_sync(0xffffffffu, rs[i][0], 1);
        rs[i][0] += __shfl_xor_sync(0xffffffffu, rs[i][0], 2);
        rs[i][1] += __shfl_xor_sync(0xffffffffu, rs[i][1], 1);
        rs[i][1] += __shfl_xor_sync(0xffffffffu, rs[i][1], 2);
        if (tig == 0) {
            size_t base = (((size_t)b * Hh + h) * MM + i) * Tt;
            g_L[base + row0]     = rs[i][0];
            g_L[base + row0 + 8] = rs[i][1];
        }
    }
}

// ---------------- pass 2: combined P @ V + fused RMSNorm ----------------
#define P2_QS_F   (128*QS_STR)
#define P2_KS_F   (64*KS_STR*2)
#define P2_VS_F   (64*KS_STR*2)
#define P2_LINV_F (MM*128)
#define P2_GM_F   128
#define P2_SMEM_BYTES ((P2_QS_F + P2_KS_F + P2_VS_F + P2_LINV_F + P2_GM_F) * 4)

__global__ __launch_bounds__(256, 1)
void attn_pass2(const float* __restrict__ raw_w,
                const float* __restrict__ wscale,
                const float* __restrict__ gamma)
{
    extern __shared__ float sm[];
    float*  qs   = sm;
    float2* ks2  = (float2*)(sm + P2_QS_F);
    float2* vs2  = (float2*)(sm + P2_QS_F + P2_KS_F);
    float*  linv = sm + P2_QS_F + P2_KS_F + P2_VS_F;
    float*  gms  = linv + P2_LINV_F;

    const int tid = threadIdx.x;
    const int lane = tid & 31, w = tid >> 5;
    const int g = lane >> 2, tig = lane & 3;
    const int qt = blockIdx.x, h = blockIdx.y, b = blockIdx.z;
    const int kvg = h >> 2;
    const int t0 = qt * 128;
    const int row0 = t0 + w * 16 + g;

    if (tid < 128) {
        float ws = wscale[0];
#pragma unroll
        for (int i = 0; i < MM; ++i) {
            float wi = tanhf(raw_w[i]) * ws;
            float l = g_L[(((size_t)b * Hh + h) * MM + i) * Tt + t0 + tid];
            linv[i * 128 + tid] = wi / l;
        }
        gms[tid] = gamma[tid];
    }
    load_q_tile(g_q + ((size_t)(b * Tt + t0)) * Ee + h * 128, qs, tid);

    float o[16][4];
#pragma unroll
    for (int nt = 0; nt < 16; ++nt)
#pragma unroll
        for (int r = 0; r < 4; ++r) o[nt][r] = 0.f;

    const int nst = 2 * qt + 2;
    float4 pf[8];
    ldg_tile(g_k + ((size_t)(b * Tt)) * EKV + kvg * 128, pf, tid);

    for (int st = 0; st < nst; ++st) {
        int s0 = st * 64;
        sts_split(pf, ks2, tid);                       // K(st) -> smem
        ldg_tile(g_v + ((size_t)(b * Tt + s0)) * EKV + kvg * 128, pf, tid);  // V(st) in flight
        __syncthreads();

        const bool active = (s0 <= t0 + w * 16 + 15);
        const bool full   = (s0 + 63 <= t0 + w * 16);
        float p[8][4];

        if (active) {
#pragma unroll
            for (int nt = 0; nt < 8; ++nt)
#pragma unroll
                for (int r = 0; r < 4; ++r) p[nt][r] = 0.f;
#pragma unroll
            for (int i = 0; i < MM; ++i) {
                float sc[8][4];
#pragma unroll
                for (int nt = 0; nt < 8; ++nt)
#pragma unroll
                    for (int r = 0; r < 4; ++r) sc[nt][r] = 0.f;
                qk_member(qs + (w * 16 + g) * QS_STR + i * HD + tig,
                          ks2 + g * KS_STR + i * HD + tig, sc);
                float l0 = linv[i * 128 + w * 16 + g];
                float l1 = linv[i * 128 + w * 16 + g + 8];
                if (full) {
#pragma unroll
                    for (int nt = 0; nt < 8; ++nt) {
                        p[nt][0] += l0 * __expf(sc[nt][0] * SCALEF);
                        p[nt][1] += l0 * __expf(sc[nt][1] * SCALEF);
                        p[nt][2] += l1 * __expf(sc[nt][2] * SCALEF);
                        p[nt][3] += l1 * __expf(sc[nt][3] * SCALEF);
                    }
                } else {
#pragma unroll
                    for (int nt = 0; nt < 8; ++nt) {
                        int col = s0 + nt * 8 + tig * 2;
                        if (col     <= row0)     p[nt][0] += l0 * __expf(sc[nt][0] * SCALEF);
                        if (col + 1 <= row0)     p[nt][1] += l0 * __expf(sc[nt][1] * SCALEF);
                        if (col     <= row0 + 8) p[nt][2] += l1 * __expf(sc[nt][2] * SCALEF);
                        if (col + 1 <= row0 + 8) p[nt][3] += l1 * __expf(sc[nt][3] * SCALEF);
                    }
                }
            }
        }

        sts_split(pf, vs2, tid);                       // V(st) -> smem
        if (st + 1 < nst)
            ldg_tile(g_k + ((size_t)(b * Tt + s0 + 64)) * EKV + kvg * 128, pf, tid); // K(st+1) in flight
        __syncthreads();

        if (active) {
            // PV: rearrange P acc-layout -> A-frag via shfl, 3xTF32 mma
            const int srcA = (lane & ~3) | (tig >> 1);
            const int srcB = srcA + 2;
#pragma unroll
            for (int kc = 0; kc < 8; ++kc) {
                float c0 = p[kc][0], c1 = p[kc][1], c2 = p[kc][2], c3 = p[kc][3];
                float t0a = __shfl_sync(0xffffffffu, c0, srcA);
                float t1a = __shfl_sync(0xffffffffu, c1, srcA);
                float t0b = __shfl_sync(0xffffffffu, c0, srcB);
                float t1b = __shfl_sync(0xffffffffu, c1, srcB);
                float t2a = __shfl_sync(0xffffffffu, c2, srcA);
                float t3a = __shfl_sync(0xffffffffu, c3, srcA);
                float t2b = __shfl_sync(0xffffffffu, c2, srcB);
                float t3b = __shfl_sync(0xffffffffu, c3, srcB);
                bool odd = (tig & 1);
                float a0f = odd ? t1a : t0a;
                float a1f = odd ? t3a : t2a;
                float a2f = odd ? t1b : t0b;
                float a3f = odd ? t3b : t2b;
                float2 sp0 = tf32split(a0f), sp1 = tf32split(a1f);
                float2 sp2 = tf32split(a2f), sp3 = tf32split(a3f);
                unsigned pah[4] = {__float_as_uint(sp0.x), __float_as_uint(sp1.x),
                                   __float_as_uint(sp2.x), __float_as_uint(sp3.x)};
                unsigned pal[4] = {__float_as_uint(sp0.y), __float_as_uint(sp1.y),
                                   __float_as_uint(sp2.y), __float_as_uint(sp3.y)};
                const float2* vb  = vs2 + (kc * 8 + tig) * KS_STR + g;
                const float2* vb4 = vs2 + (kc * 8 + tig + 4) * KS_STR + g;
#pragma unroll
                for (int nt = 0; nt < 16; ++nt) {
                    float2 bh = vb[nt * 8];
                    float2 b4 = vb4[nt * 8];
                    unsigned bhh[2] = {__float_as_uint(bh.x), __float_as_uint(b4.x)};
                    unsigned bll[2] = {__float_as_uint(bh.y), __float_as_uint(b4.y)};
                    mma_tf32(o[nt], pah, bhh);
                    mma_tf32(o[nt], pal, bhh);
                    mma_tf32(o[nt], pah, bll);
                }
            }
        }
        __syncthreads();
    }

    // fused RMSNorm over the 128 dims (quad butterfly, no smem)
    float sq0 = 0.f, sq1 = 0.f;
#pragma unroll
    for (int nt = 0; nt < 16; ++nt) {
        sq0 += o[nt][0] * o[nt][0] + o[nt][1] * o[nt][1];
        sq1 += o[nt][2] * o[nt][2] + o[nt][3] * o[nt][3];
    }
    sq0 += __shfl_xor_sync(0xffffffffu, sq0, 1);
    sq0 += __shfl_xor_sync(0xffffffffu, sq0, 2);
    sq1 += __shfl_xor_sync(0xffffffffu, sq1, 1);
    sq1 += __shfl_xor_sync(0xffffffffu, sq1, 2);
    float rn0 = rsqrtf(sq0 * (1.f / 128.f) + 1e-5f);
    float rn1 = rsqrtf(sq1 * (1.f / 128.f) + 1e-5f);

#pragma unroll
    for (int nt = 0; nt < 16; ++nt) {
        float g0 = gms[nt * 8 + tig * 2];
        float g1 = gms[nt * 8 + tig * 2 + 1];
        float* p0 = g_n + ((size_t)(b * Tt + row0)) * Ee + h * 128 + nt * 8 + tig * 2;
        float* p1 = g_n + ((size_t)(b * Tt + row0 + 8)) * Ee + h * 128 + nt * 8 + tig * 2;
        *(float2*)p0 = make_float2(o[nt][0] * rn0 * g0, o[nt][1] * rn0 * g1);
        *(float2*)p1 = make_float2(o[nt][2] * rn1 * g0, o[nt][3] * rn1 * g1);
    }
}

// ============================================================
extern "C" void kernel_launch(void* const* d_in, const int* in_sizes, int n_in,
                              void* d_out, int out_size)
{
    const float* x      = (const float*)d_in[0];
    const float* cosp   = (const float*)d_in[1];
    const float* sinp   = (const float*)d_in[2];
    const float* q_w    = (const float*)d_in[3];
    const float* k_w    = (const float*)d_in[4];
    const float* v_w    = (const float*)d_in[5];
    const float* out_w  = (const float*)d_in[6];
    const float* raw_w  = (const float*)d_in[7];
    const float* wscale = (const float*)d_in[8];
    const float* gamma  = (const float*)d_in[9];

    float *qb, *kb, *vb, *nb;
    cudaGetSymbolAddress((void**)&qb, g_q);
    cudaGetSymbolAddress((void**)&kb, g_k);
    cudaGetSymbolAddress((void**)&vb, g_v);
    cudaGetSymbolAddress((void**)&nb, g_n);

    cudaFuncSetAttribute(gemm_tf32_v2<0>, cudaFuncAttributeMaxDynamicSharedMemorySize, G_SMEM_BYTES);
    cudaFuncSetAttribute(gemm_tf32_v2<1>, cudaFuncAttributeMaxDynamicSharedMemorySize, G_SMEM_BYTES);
    cudaFuncSetAttribute(attn_pass1, cudaFuncAttributeMaxDynamicSharedMemorySize, P1_SMEM_BYTES);
    cudaFuncSetAttribute(attn_pass2, cudaFuncAttributeMaxDynamicSharedMemorySize, P2_SMEM_BYTES);

    // projections on tensor cores (rope fused into q,k)
    gemm_tf32_v2<1><<<dim3(Ee / 128, BT / 128), 256, G_SMEM_BYTES>>>(x, q_w, qb, Ee, Ee, cosp, sinp);
    gemm_tf32_v2<1><<<dim3(EKV / 128, BT / 128), 256, G_SMEM_BYTES>>>(x, k_w, kb, EKV, Ee, cosp, sinp);
    gemm_tf32_v2<0><<<dim3(EKV / 128, BT / 128), 256, G_SMEM_BYTES>>>(x, v_w, vb, EKV, Ee, nullptr, nullptr);

    // attention (2-pass, 3xTF32 mma, fused RMSNorm, reg-prefetch)
    dim3 agrid(Tt / 128, Hh, Bb);
    attn_pass1<<<agrid, 256, P1_SMEM_BYTES>>>();
    attn_pass2<<<agrid, 256, P2_SMEM_BYTES>>>(raw_w, wscale, gamma);

    // output projection on tensor cores
    gemm_tf32_v2<0><<<dim3(Ee / 128, BT / 128), 256, G_SMEM_BYTES>>>(nb, out_w, (float*)d_out, Ee, Ee, nullptr, nullptr);
}